// round 15
// baseline (speedup 1.0000x reference)
#include <cuda_runtime.h>
#include <cuda_fp16.h>
#include <cstdint>

#define QLEN 2048
#define BSZ 2
#define NH 12
#define DH 64
#define DM 768
#define NEGINF (-1e30f)
#define SCALE_L2E 0.1803368801111244f     // (1/sqrt(64)) * log2(e)

// ---------------- scratch (static device allocations) --------------------------
__device__ __half g_Qh[BSZ * NH * QLEN * DH];   // [b][n][i][d], pre-scaled by SCALE_L2E
__device__ __half g_Kh[BSZ * NH * QLEN * DH];   // [b][n][j][d]
__device__ __half g_Vt[BSZ * NH * DH * QLEN];   // [b][n][d][j]  (transposed)
__device__ __half g_Rh[NH * QLEN * DH];         // [n][m][d]
__device__ __half g_wh[QLEN * BSZ * DM];        // fp16 copy of w
__device__ __half g_qkvwh[3 * DM * DM];         // fp16 copy of qkv_w
__device__ __half g_owh[DM * DM];               // fp16 copy of o_w
__device__ __half g_atth[QLEN * BSZ * DM];      // attn_vec fp16, row r = i*BSZ+b
__device__ float g_res[QLEN * BSZ * DM];        // w + attn_out

__device__ __forceinline__ uint32_t smem_u32(const void* p) {
    uint32_t a;
    asm("{ .reg .u64 t; cvta.to.shared.u64 t, %1; cvt.u32.u64 %0, t; }" : "=r"(a) : "l"(p));
    return a;
}
__device__ __forceinline__ void cp16(uint32_t dst, const void* src, uint32_t srcsize) {
    asm volatile("cp.async.cg.shared.global [%0], [%1], 16, %2;"
                 :: "r"(dst), "l"(src), "r"(srcsize) : "memory");
}
#define CP_COMMIT() asm volatile("cp.async.commit_group;" ::: "memory")
#define CP_WAIT0()  asm volatile("cp.async.wait_group 0;" ::: "memory")
#define CP_WAIT1()  asm volatile("cp.async.wait_group 1;" ::: "memory")

#define MMA_FP16(d, a, b)                                                          \
    asm volatile("mma.sync.aligned.m16n8k16.row.col.f32.f16.f16.f32 "              \
                 "{%0,%1,%2,%3}, {%4,%5,%6,%7}, {%8,%9}, {%0,%1,%2,%3};"           \
                 : "+f"((d)[0]), "+f"((d)[1]), "+f"((d)[2]), "+f"((d)[3])          \
                 : "r"((a)[0]), "r"((a)[1]), "r"((a)[2]), "r"((a)[3]),             \
                   "r"((b)[0]), "r"((b)[1]))

// fast 2^t for t <= 0 (clamped); deg-4 Taylor in f*ln2; rel err <= ~9e-5
__device__ __forceinline__ float exp2_poly(float t) {
    t = fmaxf(t, -100.f);
    const float r = rintf(t);
    const float y = (t - r) * 0.6931471805599453f;
    float p = 0.041666667f;
    p = p * y + 0.166666667f;
    p = p * y + 0.5f;
    p = p * y + 1.0f;
    p = p * y + 1.0f;
    const int ri = (int)r;
    return p * __int_as_float((ri + 127) << 23);
}

// ================= fp32 -> fp16 conversion pre-pass ============================
#define NW  (QLEN * BSZ * DM)
#define NQW (3 * DM * DM)
#define NOW (DM * DM)
__global__ void __launch_bounds__(256) f2h_kernel(const float* __restrict__ w,
                                                  const float* __restrict__ qkv_w,
                                                  const float* __restrict__ o_w) {
    const int stride = gridDim.x * 256 * 4;
    for (int i = (blockIdx.x * 256 + threadIdx.x) * 4; i < NW + NQW + NOW; i += stride) {
        float4 v;
        __half2* dst;
        if (i < NW) {
            v = *(const float4*)(w + i);
            dst = (__half2*)(g_wh + i);
        } else if (i < NW + NQW) {
            v = *(const float4*)(qkv_w + (i - NW));
            dst = (__half2*)(g_qkvwh + (i - NW));
        } else {
            v = *(const float4*)(o_w + (i - NW - NQW));
            dst = (__half2*)(g_owh + (i - NW - NQW));
        }
        dst[0] = __floats2half2_rn(v.x, v.y);
        dst[1] = __floats2half2_rn(v.z, v.w);
    }
}

// ================= pure-fp16 cp.async projection GEMM (unchanged, R14 win) =====
#define PBM 128
#define PBN 128
#define PBK 64
#define PLH 72
#define PSTG_BYTES ((PBM + PBN) * PLH * 2)
#define PROJ_SMEM_BYTES (2 * PSTG_BYTES)

__device__ __forceinline__ void proj_issue_h(const __half* A, const __half* B,
                                             int rb, int cb, int kdim, int tid,
                                             uint32_t sb, int k0) {
#pragma unroll
    for (int e2 = 0; e2 < 8; e2++) {
        const int e = tid + e2 * 256;
        const int row = (e & 1023) >> 3, c4 = e & 7;
        if (e < 1024) {
            cp16(sb + (uint32_t)(row * PLH * 2 + c4 * 16),
                 A + (size_t)(rb + row) * kdim + k0 + c4 * 8, 16);
        } else {
            cp16(sb + (uint32_t)((PBM + row) * PLH * 2 + c4 * 16),
                 B + (size_t)(cb + row) * kdim + k0 + c4 * 8, 16);
        }
    }
    CP_COMMIT();
}

template <int MODE>
__global__ void __launch_bounds__(256, 2) mma_gemm_kernel(const __half* __restrict__ A,
                                                          const __half* __restrict__ B,
                                                          const float* __restrict__ W,
                                                          int kdim) {
    extern __shared__ char psm[];
    const uint32_t smb = smem_u32(psm);

    const int tid = threadIdx.x;
    const int wid = tid >> 5, lane = tid & 31;
    const int wm = wid & 3;
    const int wn = wid >> 2;
    const int rb = blockIdx.x * PBM;
    const int cb = blockIdx.y * PBN;
    const int lq = lane >> 2;
    const int lr = lane & 3;

    const int nchunk = kdim / PBK;

    float acc[2][8][4];
#pragma unroll
    for (int mt = 0; mt < 2; mt++)
#pragma unroll
        for (int nt = 0; nt < 8; nt++)
#pragma unroll
            for (int u = 0; u < 4; u++) acc[mt][nt][u] = 0.f;

    proj_issue_h(A, B, rb, cb, kdim, tid, smb, 0);
    if (nchunk > 1) proj_issue_h(A, B, rb, cb, kdim, tid, smb + PSTG_BYTES, PBK);

    for (int c = 0; c < nchunk; c++) {
        if (c + 1 < nchunk) { CP_WAIT1(); } else { CP_WAIT0(); }
        __syncthreads();

        const char* As = psm + (c & 1) * PSTG_BYTES;
        const char* Bs = As + PBM * PLH * 2;
#pragma unroll
        for (int kk = 0; kk < PBK / 16; kk++) {
            const int c0 = kk * 16 + 2 * lr;
            uint32_t af[2][4];
#pragma unroll
            for (int mt = 0; mt < 2; mt++) {
                const int ar = wm * 32 + mt * 16 + lq;
                af[mt][0] = *(const uint32_t*)(As + (ar * PLH + c0) * 2);
                af[mt][1] = *(const uint32_t*)(As + ((ar + 8) * PLH + c0) * 2);
                af[mt][2] = *(const uint32_t*)(As + (ar * PLH + c0 + 8) * 2);
                af[mt][3] = *(const uint32_t*)(As + ((ar + 8) * PLH + c0 + 8) * 2);
            }
            uint32_t bf[8][2];
#pragma unroll
            for (int nt = 0; nt < 8; nt++) {
                const int bc = wn * 64 + nt * 8 + lq;
                bf[nt][0] = *(const uint32_t*)(Bs + (bc * PLH + c0) * 2);
                bf[nt][1] = *(const uint32_t*)(Bs + (bc * PLH + c0 + 8) * 2);
            }
#pragma unroll
            for (int mt = 0; mt < 2; mt++)
#pragma unroll
                for (int nt = 0; nt < 8; nt++)
                    MMA_FP16(acc[mt][nt], af[mt], bf[nt]);
        }
        __syncthreads();
        if (c + 2 < nchunk)
            proj_issue_h(A, B, rb, cb, kdim, tid,
                         smb + (uint32_t)(c & 1) * PSTG_BYTES, (c + 2) * PBK);
    }

#pragma unroll
    for (int mt = 0; mt < 2; mt++) {
#pragma unroll
        for (int half = 0; half < 2; half++) {
            const int r = rb + wm * 32 + mt * 16 + lq + half * 8;
#pragma unroll
            for (int nt = 0; nt < 8; nt++) {
                const int h = cb + wn * 64 + nt * 8 + lr * 2;
                const float v0 = acc[mt][nt][half * 2 + 0];
                const float v1 = acc[mt][nt][half * 2 + 1];
                if (MODE == 0) {
                    const int i = r >> 1, b = r & 1;
                    const int sel = h / DM;
                    const int rem = h - sel * DM;
                    const int n = rem >> 6, d0 = rem & 63;
                    if (sel == 0) {
                        __half2 p = __floats2half2_rn(v0 * SCALE_L2E, v1 * SCALE_L2E);
                        *(__half2*)(g_Qh + ((size_t)(b * NH + n) * QLEN + i) * DH + d0) = p;
                    } else if (sel == 1) {
                        __half2 p = __floats2half2_rn(v0, v1);
                        *(__half2*)(g_Kh + ((size_t)(b * NH + n) * QLEN + i) * DH + d0) = p;
                    } else {
                        g_Vt[((size_t)(b * NH + n) * DH + d0) * QLEN + i] = __float2half(v0);
                        g_Vt[((size_t)(b * NH + n) * DH + d0 + 1) * QLEN + i] = __float2half(v1);
                    }
                } else {
                    const float2 wv = *(const float2*)(W + (size_t)r * DM + h);
                    *(float2*)(g_res + (size_t)r * DM + h) =
                        make_float2(v0 + wv.x, v1 + wv.y);
                }
            }
        }
    }
}

// ================= r_emb -> fp16 head-major ===================================
__global__ void __launch_bounds__(256) conv_r_kernel(const float* __restrict__ r_emb) {
    const int m = blockIdx.x;
    const int tid = threadIdx.x;
#pragma unroll
    for (int u = 0; u < 3; u++) {
        const int e = tid + u * 256;
        const int n = e >> 6, d = e & 63;
        g_Rh[((size_t)n * QLEN + m) * DH + d] =
            __float2half(r_emb[(size_t)m * NH * DH + e]);
    }
}

// ================= Kernel 2: 512-thread fp16 flash rel-attention ===============
#define LH 72                                 // fp16 row stride (144 B)
#define LST 196                               // fp32 score row stride
#define SG_KR 0
#define SG_V  (192 * LH * 2)                  // 27648
#define SG_RB (SG_V + 64 * LH * 2)            // 36864
#define STAGE_BYTES (SG_RB + 128 * 4)         // 37376
#define OF_ST  (2 * STAGE_BYTES)              // 74752 : STs fp32 64x196
#define OF_PQ  (OF_ST + 64 * LST * 4)         // 124928 : P/Q fp16 64x72
#define OF_BW  (OF_PQ + 64 * LH * 2)          // 134144
#define OF_BK  (OF_BW + 256)
#define OF_CSC (OF_BK + 256)
#define OF_LI  (OF_CSC + 256)
#define ATTN_SMEM_BYTES (OF_LI + 256)         // 135168

__global__ void __launch_bounds__(512, 1) attn_kernel(const float* __restrict__ r_bias,
                                                      const float* __restrict__ r_w_bias) {
    extern __shared__ char sm[];
    const uint32_t smb = smem_u32(sm);
    float* STs = (float*)(sm + OF_ST);
    __half* Ph = (__half*)(sm + OF_PQ);
    float* Bws = (float*)(sm + OF_BW);
    float* Bks = (float*)(sm + OF_BK);
    float* cscs = (float*)(sm + OF_CSC);
    float* lis  = (float*)(sm + OF_LI);

    const int bn = blockIdx.y;
    const int b = bn / NH, n = bn % NH;
    const int it = (gridDim.x - 1) - blockIdx.x;   // longest blocks first
    const int i0 = it * 64;
    const int tid = threadIdx.x;
    const int wid = tid >> 5, lane = tid & 31;
    const int wm = wid & 3;          // 4 warp-rows x 16
    const int wn = wid >> 2;         // 4 warp-cols: ST 4 x 48, PV 4 x 16
    const int lq = lane >> 2, lr = lane & 3;

    const __half* Kg0 = g_Kh + (size_t)(b * NH + n) * QLEN * DH;
    const __half* Vt0 = g_Vt + (size_t)(b * NH + n) * DH * QLEN;
    const __half* Rg0 = g_Rh + (size_t)n * QLEN * DH;

    // ---- prologue: Q tile into Ph (512 chunks of 16B = 1/thread), r_w_bias ----
    {
        const __half* Qg = g_Qh + ((size_t)(b * NH + n) * QLEN + i0) * DH;
        const int row = tid >> 3, c4 = tid & 7;
        *(uint4*)((char*)Ph + row * (LH * 2) + c4 * 16) =
            *(const uint4*)(Qg + row * DH + c4 * 8);
        if (tid < 64) Bws[tid] = r_w_bias[n * DH + tid] * SCALE_L2E;
    }

    // ---- prologue: cp.async stage 0 (2048 chunks = 4/thread) ----
    {
        const int m0 = 1984 - i0;
#pragma unroll
        for (int e2 = 0; e2 < 4; e2++) {
            const int e = tid + e2 * 512;
            const int row = e >> 3, c4 = e & 7;
            if (row < 64) {
                cp16(smb + SG_KR + row * (LH * 2) + c4 * 16, Kg0 + row * DH + c4 * 8, 16);
            } else if (row < 192) {
                const int rr = row - 64;
                const int m = m0 + rr;
                const uint32_t ok = (rr < 127 && m < QLEN) ? 16u : 0u;
                const __half* src = Rg0 + (size_t)(ok ? m : 0) * DH + c4 * 8;
                cp16(smb + SG_KR + row * (LH * 2) + c4 * 16, src, ok);
            } else {
                const int d = row - 192;
                cp16(smb + SG_V + d * (LH * 2) + c4 * 16, Vt0 + (size_t)d * QLEN + c4 * 8, 16);
            }
        }
        CP_COMMIT();
        if (tid < 128) {
            const int m = m0 + tid;
            ((float*)(sm + SG_RB))[tid] =
                (tid < 127 && m < QLEN) ? r_bias[m * NH + n] * SCALE_L2E : 0.f;
        }
    }
    __syncthreads();

    // Q fragments -> registers (rows wm*16 + lq, +8)
    uint32_t af[4][4];
    {
        const int qr = wm * 16 + lq;
        const char* Pb = (char*)Ph;
#pragma unroll
        for (int kk = 0; kk < 4; kk++) {
            const int c0 = kk * 16 + 2 * lr;
            af[kk][0] = *(const uint32_t*)(Pb + (qr * LH + c0) * 2);
            af[kk][1] = *(const uint32_t*)(Pb + ((qr + 8) * LH + c0) * 2);
            af[kk][2] = *(const uint32_t*)(Pb + (qr * LH + c0 + 8) * 2);
            af[kk][3] = *(const uint32_t*)(Pb + ((qr + 8) * LH + c0 + 8) * 2);
        }
    }

    float oacc[2][4];
#pragma unroll
    for (int nt = 0; nt < 2; nt++)
#pragma unroll
        for (int u = 0; u < 4; u++) oacc[nt][u] = 0.f;

    // softmax row state: row = tid>>3 (8 threads/row), q8 = tid&7
    const int srow = tid >> 3;
    const int q8 = tid & 7;
    float mi = NEGINF, li = 0.f;

    const int njt = it + 1;
    for (int jt = 0; jt < njt; jt++) {
        const bool diag = (jt == it);
        const char* SGc = sm + (jt & 1) * STAGE_BYTES;
        const char* KRb = SGc + SG_KR;
        const char* Vtb = SGc + SG_V;
        const float* Rbcur = (const float*)(SGc + SG_RB);

        CP_WAIT0();
        __syncthreads();

        // ---- prefetch stage jt+1 ----
        if (jt + 1 < njt) {
            const int j0n = (jt + 1) * 64;
            const int m0n = 1984 - i0 + j0n;
            const uint32_t nb = smb + ((jt + 1) & 1) * STAGE_BYTES;
            const __half* Kgn = Kg0 + (size_t)j0n * DH;
#pragma unroll
            for (int e2 = 0; e2 < 4; e2++) {
                const int e = tid + e2 * 512;
                const int row = e >> 3, c4 = e & 7;
                if (row < 64) {
                    cp16(nb + SG_KR + row * (LH * 2) + c4 * 16, Kgn + row * DH + c4 * 8, 16);
                } else if (row < 192) {
                    const int rr = row - 64;
                    const int m = m0n + rr;
                    const uint32_t ok = (rr < 127 && m < QLEN) ? 16u : 0u;
                    const __half* src = Rg0 + (size_t)(ok ? m : 0) * DH + c4 * 8;
                    cp16(nb + SG_KR + row * (LH * 2) + c4 * 16, src, ok);
                } else {
                    const int d = row - 192;
                    cp16(nb + SG_V + d * (LH * 2) + c4 * 16,
                         Vt0 + (size_t)d * QLEN + j0n + c4 * 8, 16);
                }
            }
            CP_COMMIT();
            if (tid < 128) {
                const int m = m0n + tid;
                ((float*)(sm + ((jt + 1) & 1) * STAGE_BYTES + SG_RB))[tid] =
                    (tid < 127 && m < QLEN) ? r_bias[m * NH + n] * SCALE_L2E : 0.f;
            }
        }

        // Bk[j] = (rwb*s) . k_j   (warps 0-1)
        if (tid < 64) {
            float s = 0.f;
            const __half2* krow = (const __half2*)(KRb + tid * (LH * 2));
#pragma unroll
            for (int dd = 0; dd < 32; dd++) {
                float2 kv = __half22float2(krow[dd]);
                s += Bws[dd * 2] * kv.x + Bws[dd * 2 + 1] * kv.y;
            }
            Bks[tid] = s;
        }

        // ---- ST = Q . KR^T  (64 x 192; warp = 16 rows x 48 cols) ----
        {
            float sacc[6][4];
#pragma unroll
            for (int nt = 0; nt < 6; nt++)
#pragma unroll
                for (int u = 0; u < 4; u++) sacc[nt][u] = 0.f;
#pragma unroll
            for (int kk = 0; kk < 4; kk++) {
                const int c0 = kk * 16 + 2 * lr;
                uint32_t bf[6][2];
#pragma unroll
                for (int nt = 0; nt < 6; nt++) {
                    const int bc = wn * 48 + nt * 8 + lq;
                    bf[nt][0] = *(const uint32_t*)(KRb + (bc * LH + c0) * 2);
                    bf[nt][1] = *(const uint32_t*)(KRb + (bc * LH + c0 + 8) * 2);
                }
#pragma unroll
                for (int nt = 0; nt < 6; nt++)
                    MMA_FP16(sacc[nt], af[kk], bf[nt]);
            }
            const int row0 = wm * 16 + lq;
#pragma unroll
            for (int nt = 0; nt < 6; nt++) {
                const int col = wn * 48 + nt * 8 + lr * 2;
                *(float2*)&STs[row0 * LST + col] = make_float2(sacc[nt][0], sacc[nt][1]);
                *(float2*)&STs[(row0 + 8) * LST + col] = make_float2(sacc[nt][2], sacc[nt][3]);
            }
        }
        __syncthreads();

        // ---- softmax (8 threads/row, 8 cols each) ----
        {
            const int toff = 127 - srow;
            const int roff = 63 - srow;
            float z[8];
            float lmax = NEGINF;
#pragma unroll
            for (int c = 0; c < 8; c++) {
                const int jl = q8 + 8 * c;
                float s = STs[srow * LST + jl] + STs[srow * LST + toff + jl] +
                          Bks[jl] + Rbcur[roff + jl];
                if (diag && jl > srow) s = NEGINF;
                z[c] = s;
                lmax = fmaxf(lmax, s);
            }
            lmax = fmaxf(lmax, __shfl_xor_sync(0xffffffffu, lmax, 1));
            lmax = fmaxf(lmax, __shfl_xor_sync(0xffffffffu, lmax, 2));
            lmax = fmaxf(lmax, __shfl_xor_sync(0xffffffffu, lmax, 4));
            const float mnew = fmaxf(mi, lmax);
            const float csc = exp2_poly(mi - mnew);
            float lsum = 0.f;
#pragma unroll
            for (int c = 0; c < 8; c++) {
                const float p = exp2_poly(z[c] - mnew);
                Ph[srow * LH + q8 + 8 * c] = __float2half(p);
                lsum += p;
            }
            lsum += __shfl_xor_sync(0xffffffffu, lsum, 1);
            lsum += __shfl_xor_sync(0xffffffffu, lsum, 2);
            lsum += __shfl_xor_sync(0xffffffffu, lsum, 4);
            li = li * csc + lsum;
            mi = mnew;
            if (q8 == 0) cscs[srow] = csc;
        }
        __syncthreads();

        // ---- O = O*csc + P.V   (warp = 16 rows x 16 cols) ----
        {
            const int ar = wm * 16 + lq;
            const float c0 = cscs[ar];
            const float c1 = cscs[ar + 8];
#pragma unroll
            for (int nt = 0; nt < 2; nt++) {
                oacc[nt][0] *= c0; oacc[nt][1] *= c0;
                oacc[nt][2] *= c1; oacc[nt][3] *= c1;
            }
            const char* Pb = (char*)Ph;
#pragma unroll
            for (int kk = 0; kk < 4; kk++) {
                const int c0k = kk * 16 + 2 * lr;
                uint32_t pa[4];
                pa[0] = *(const uint32_t*)(Pb + (ar * LH + c0k) * 2);
                pa[1] = *(const uint32_t*)(Pb + ((ar + 8) * LH + c0k) * 2);
                pa[2] = *(const uint32_t*)(Pb + (ar * LH + c0k + 8) * 2);
                pa[3] = *(const uint32_t*)(Pb + ((ar + 8) * LH + c0k + 8) * 2);
#pragma unroll
                for (int nt = 0; nt < 2; nt++) {
                    const int d = wn * 16 + nt * 8 + lq;
                    uint32_t vb[2];
                    vb[0] = *(const uint32_t*)(Vtb + (d * LH + c0k) * 2);
                    vb[1] = *(const uint32_t*)(Vtb + (d * LH + c0k + 8) * 2);
                    MMA_FP16(oacc[nt], pa, vb);
                }
            }
        }
    }

    // ---- epilogue: write attn_vec in fp16 for the O-projection ----
    if (q8 == 0) lis[srow] = li;
    __syncthreads();
    {
        const int r0 = wm * 16 + lq;
        const float inv0 = 1.f / lis[r0];
        const float inv1 = 1.f / lis[r0 + 8];
#pragma unroll
        for (int nt = 0; nt < 2; nt++) {
            const int d = wn * 16 + nt * 8 + lr * 2;
            __half* p0 = g_atth + ((size_t)(i0 + r0) * BSZ + b) * DM + n * DH + d;
            *(__half2*)p0 = __floats2half2_rn(oacc[nt][0] * inv0, oacc[nt][1] * inv0);
            __half* p1 = g_atth + ((size_t)(i0 + r0 + 8) * BSZ + b) * DM + n * DH + d;
            *(__half2*)p1 = __floats2half2_rn(oacc[nt][2] * inv1, oacc[nt][3] * inv1);
        }
    }
}

// ================= Kernel 4: LayerNorm ========================================
__device__ __forceinline__ float block_sum(float v, float* red) {
#pragma unroll
    for (int o = 16; o > 0; o >>= 1) v += __shfl_xor_sync(0xffffffffu, v, o);
    const int w = threadIdx.x >> 5;
    if ((threadIdx.x & 31) == 0) red[w] = v;
    __syncthreads();
    if (threadIdx.x < 32) {
        float t = (threadIdx.x < 8) ? red[threadIdx.x] : 0.f;
#pragma unroll
        for (int o = 4; o > 0; o >>= 1) t += __shfl_xor_sync(0xffffffffu, t, o);
        if (threadIdx.x == 0) red[0] = t;
    }
    __syncthreads();
    const float r = red[0];
    __syncthreads();
    return r;
}

__global__ void __launch_bounds__(256) ln_kernel(const float* __restrict__ gamma,
                                                 const float* __restrict__ beta,
                                                 float* __restrict__ out) {
    __shared__ float red[8];
    const int r = blockIdx.x;
    const float* x = g_res + (size_t)r * DM;
    const int tid = threadIdx.x;
    float v[3];
#pragma unroll
    for (int u = 0; u < 3; u++) v[u] = x[tid + u * 256];
    const float total = block_sum(v[0] + v[1] + v[2], red);
    const float mu = total * (1.f / DM);
    float sq = 0.f;
#pragma unroll
    for (int u = 0; u < 3; u++) { const float d = v[u] - mu; sq += d * d; }
    const float var = block_sum(sq, red) * (1.f / DM);
    const float inv = rsqrtf(var + 1e-5f);
#pragma unroll
    for (int u = 0; u < 3; u++) {
        const int c = tid + u * 256;
        out[(size_t)r * DM + c] = (v[u] - mu) * inv * gamma[c] + beta[c];
    }
}

// ================= launch =====================================================
extern "C" void kernel_launch(void* const* d_in, const int* in_sizes, int n_in,
                              void* d_out, int out_size) {
    const float* w        = (const float*)d_in[0];
    const float* r_emb    = (const float*)d_in[1];
    const float* r_w_bias = (const float*)d_in[2];
    const float* r_bias   = (const float*)d_in[3];
    const float* qkv_w    = (const float*)d_in[4];
    const float* o_w      = (const float*)d_in[5];
    const float* ln_g     = (const float*)d_in[6];
    const float* ln_b     = (const float*)d_in[7];
    float* out = (float*)d_out;

    __half *g_wh_p = nullptr, *g_qkvwh_p = nullptr, *g_owh_p = nullptr, *g_atth_p = nullptr;
    cudaGetSymbolAddress((void**)&g_wh_p, g_wh);
    cudaGetSymbolAddress((void**)&g_qkvwh_p, g_qkvwh);
    cudaGetSymbolAddress((void**)&g_owh_p, g_owh);
    cudaGetSymbolAddress((void**)&g_atth_p, g_atth);

    f2h_kernel<<<1024, 256>>>(w, qkv_w, o_w);
    conv_r_kernel<<<QLEN, 256>>>(r_emb);

    (void)cudaFuncSetAttribute(mma_gemm_kernel<0>,
                               cudaFuncAttributeMaxDynamicSharedMemorySize, PROJ_SMEM_BYTES);
    (void)cudaFuncSetAttribute(mma_gemm_kernel<1>,
                               cudaFuncAttributeMaxDynamicSharedMemorySize, PROJ_SMEM_BYTES);

    // QKV projection -> fp16 Q/K/Vt
    mma_gemm_kernel<0><<<dim3(QLEN * BSZ / PBM, 3 * DM / PBN), 256, PROJ_SMEM_BYTES>>>(
        g_wh_p, g_qkvwh_p, nullptr, DM);

    // 512-thread fp16 flash rel-attention
    (void)cudaFuncSetAttribute(attn_kernel, cudaFuncAttributeMaxDynamicSharedMemorySize,
                               ATTN_SMEM_BYTES);
    attn_kernel<<<dim3(QLEN / 64, BSZ * NH), 512, ATTN_SMEM_BYTES>>>(r_bias, r_w_bias);

    // O-projection + residual
    mma_gemm_kernel<1><<<dim3(QLEN * BSZ / PBM, DM / PBN), 256, PROJ_SMEM_BYTES>>>(
        g_atth_p, g_owh_p, w, DM);

    ln_kernel<<<QLEN * BSZ, 256>>>(ln_g, ln_b, out);
}

// round 16
// speedup vs baseline: 1.1380x; 1.1380x over previous
#include <cuda_runtime.h>
#include <cuda_fp16.h>
#include <cstdint>

#define QLEN 2048
#define BSZ 2
#define NH 12
#define DH 64
#define DM 768
#define NEGINF (-1e30f)
#define SCALE_L2E 0.1803368801111244f     // (1/sqrt(64)) * log2(e)

// ---------------- scratch (static device allocations) --------------------------
__device__ __half g_Qh[BSZ * NH * QLEN * DH];   // [b][n][i][d], pre-scaled by SCALE_L2E
__device__ __half g_Kh[BSZ * NH * QLEN * DH];   // [b][n][j][d]
__device__ __half g_Vt[BSZ * NH * DH * QLEN];   // [b][n][d][j]  (transposed)
__device__ __half g_Rh[NH * QLEN * DH];         // [n][m][d]
__device__ __half g_wh[QLEN * BSZ * DM];        // fp16 copy of w
__device__ __half g_qkvwh[3 * DM * DM];         // fp16 copy of qkv_w
__device__ __half g_owh[DM * DM];               // fp16 copy of o_w
__device__ __half g_atth[QLEN * BSZ * DM];      // attn_vec fp16, row r = i*BSZ+b
__device__ float g_res[QLEN * BSZ * DM];        // w + attn_out

__device__ __forceinline__ uint32_t smem_u32(const void* p) {
    uint32_t a;
    asm("{ .reg .u64 t; cvta.to.shared.u64 t, %1; cvt.u32.u64 %0, t; }" : "=r"(a) : "l"(p));
    return a;
}
__device__ __forceinline__ void cp16(uint32_t dst, const void* src, uint32_t srcsize) {
    asm volatile("cp.async.cg.shared.global [%0], [%1], 16, %2;"
                 :: "r"(dst), "l"(src), "r"(srcsize) : "memory");
}
#define CP_COMMIT() asm volatile("cp.async.commit_group;" ::: "memory")
#define CP_WAIT0()  asm volatile("cp.async.wait_group 0;" ::: "memory")
#define CP_WAIT1()  asm volatile("cp.async.wait_group 1;" ::: "memory")
#define BAR_PAIR(id) asm volatile("bar.sync %0, 64;" :: "r"(id) : "memory")

#define MMA_FP16(d, a, b)                                                          \
    asm volatile("mma.sync.aligned.m16n8k16.row.col.f32.f16.f16.f32 "              \
                 "{%0,%1,%2,%3}, {%4,%5,%6,%7}, {%8,%9}, {%0,%1,%2,%3};"           \
                 : "+f"((d)[0]), "+f"((d)[1]), "+f"((d)[2]), "+f"((d)[3])          \
                 : "r"((a)[0]), "r"((a)[1]), "r"((a)[2]), "r"((a)[3]),             \
                   "r"((b)[0]), "r"((b)[1]))

// fast 2^t for t <= 0 (clamped); deg-4 Taylor in f*ln2; rel err <= ~9e-5
__device__ __forceinline__ float exp2_poly(float t) {
    t = fmaxf(t, -100.f);
    const float r = rintf(t);
    const float y = (t - r) * 0.6931471805599453f;
    float p = 0.041666667f;
    p = p * y + 0.166666667f;
    p = p * y + 0.5f;
    p = p * y + 1.0f;
    p = p * y + 1.0f;
    const int ri = (int)r;
    return p * __int_as_float((ri + 127) << 23);
}

// ================= fp32 -> fp16 conversion pre-pass ============================
#define NW  (QLEN * BSZ * DM)
#define NQW (3 * DM * DM)
#define NOW (DM * DM)
__global__ void __launch_bounds__(256) f2h_kernel(const float* __restrict__ w,
                                                  const float* __restrict__ qkv_w,
                                                  const float* __restrict__ o_w) {
    const int stride = gridDim.x * 256 * 4;
    for (int i = (blockIdx.x * 256 + threadIdx.x) * 4; i < NW + NQW + NOW; i += stride) {
        float4 v;
        __half2* dst;
        if (i < NW) {
            v = *(const float4*)(w + i);
            dst = (__half2*)(g_wh + i);
        } else if (i < NW + NQW) {
            v = *(const float4*)(qkv_w + (i - NW));
            dst = (__half2*)(g_qkvwh + (i - NW));
        } else {
            v = *(const float4*)(o_w + (i - NW - NQW));
            dst = (__half2*)(g_owh + (i - NW - NQW));
        }
        dst[0] = __floats2half2_rn(v.x, v.y);
        dst[1] = __floats2half2_rn(v.z, v.w);
    }
}

// ================= pure-fp16 cp.async projection GEMM (unchanged, R14 win) =====
#define PBM 128
#define PBN 128
#define PBK 64
#define PLH 72
#define PSTG_BYTES ((PBM + PBN) * PLH * 2)
#define PROJ_SMEM_BYTES (2 * PSTG_BYTES)

__device__ __forceinline__ void proj_issue_h(const __half* A, const __half* B,
                                             int rb, int cb, int kdim, int tid,
                                             uint32_t sb, int k0) {
#pragma unroll
    for (int e2 = 0; e2 < 8; e2++) {
        const int e = tid + e2 * 256;
        const int row = (e & 1023) >> 3, c4 = e & 7;
        if (e < 1024) {
            cp16(sb + (uint32_t)(row * PLH * 2 + c4 * 16),
                 A + (size_t)(rb + row) * kdim + k0 + c4 * 8, 16);
        } else {
            cp16(sb + (uint32_t)((PBM + row) * PLH * 2 + c4 * 16),
                 B + (size_t)(cb + row) * kdim + k0 + c4 * 8, 16);
        }
    }
    CP_COMMIT();
}

template <int MODE>
__global__ void __launch_bounds__(256, 2) mma_gemm_kernel(const __half* __restrict__ A,
                                                          const __half* __restrict__ B,
                                                          const float* __restrict__ W,
                                                          int kdim) {
    extern __shared__ char psm[];
    const uint32_t smb = smem_u32(psm);

    const int tid = threadIdx.x;
    const int wid = tid >> 5, lane = tid & 31;
    const int wm = wid & 3;
    const int wn = wid >> 2;
    const int rb = blockIdx.x * PBM;
    const int cb = blockIdx.y * PBN;
    const int lq = lane >> 2;
    const int lr = lane & 3;

    const int nchunk = kdim / PBK;

    float acc[2][8][4];
#pragma unroll
    for (int mt = 0; mt < 2; mt++)
#pragma unroll
        for (int nt = 0; nt < 8; nt++)
#pragma unroll
            for (int u = 0; u < 4; u++) acc[mt][nt][u] = 0.f;

    proj_issue_h(A, B, rb, cb, kdim, tid, smb, 0);
    if (nchunk > 1) proj_issue_h(A, B, rb, cb, kdim, tid, smb + PSTG_BYTES, PBK);

    for (int c = 0; c < nchunk; c++) {
        if (c + 1 < nchunk) { CP_WAIT1(); } else { CP_WAIT0(); }
        __syncthreads();

        const char* As = psm + (c & 1) * PSTG_BYTES;
        const char* Bs = As + PBM * PLH * 2;
#pragma unroll
        for (int kk = 0; kk < PBK / 16; kk++) {
            const int c0 = kk * 16 + 2 * lr;
            uint32_t af[2][4];
#pragma unroll
            for (int mt = 0; mt < 2; mt++) {
                const int ar = wm * 32 + mt * 16 + lq;
                af[mt][0] = *(const uint32_t*)(As + (ar * PLH + c0) * 2);
                af[mt][1] = *(const uint32_t*)(As + ((ar + 8) * PLH + c0) * 2);
                af[mt][2] = *(const uint32_t*)(As + (ar * PLH + c0 + 8) * 2);
                af[mt][3] = *(const uint32_t*)(As + ((ar + 8) * PLH + c0 + 8) * 2);
            }
            uint32_t bf[8][2];
#pragma unroll
            for (int nt = 0; nt < 8; nt++) {
                const int bc = wn * 64 + nt * 8 + lq;
                bf[nt][0] = *(const uint32_t*)(Bs + (bc * PLH + c0) * 2);
                bf[nt][1] = *(const uint32_t*)(Bs + (bc * PLH + c0 + 8) * 2);
            }
#pragma unroll
            for (int mt = 0; mt < 2; mt++)
#pragma unroll
                for (int nt = 0; nt < 8; nt++)
                    MMA_FP16(acc[mt][nt], af[mt], bf[nt]);
        }
        __syncthreads();
        if (c + 2 < nchunk)
            proj_issue_h(A, B, rb, cb, kdim, tid,
                         smb + (uint32_t)(c & 1) * PSTG_BYTES, (c + 2) * PBK);
    }

#pragma unroll
    for (int mt = 0; mt < 2; mt++) {
#pragma unroll
        for (int half = 0; half < 2; half++) {
            const int r = rb + wm * 32 + mt * 16 + lq + half * 8;
#pragma unroll
            for (int nt = 0; nt < 8; nt++) {
                const int h = cb + wn * 64 + nt * 8 + lr * 2;
                const float v0 = acc[mt][nt][half * 2 + 0];
                const float v1 = acc[mt][nt][half * 2 + 1];
                if (MODE == 0) {
                    const int i = r >> 1, b = r & 1;
                    const int sel = h / DM;
                    const int rem = h - sel * DM;
                    const int n = rem >> 6, d0 = rem & 63;
                    if (sel == 0) {
                        __half2 p = __floats2half2_rn(v0 * SCALE_L2E, v1 * SCALE_L2E);
                        *(__half2*)(g_Qh + ((size_t)(b * NH + n) * QLEN + i) * DH + d0) = p;
                    } else if (sel == 1) {
                        __half2 p = __floats2half2_rn(v0, v1);
                        *(__half2*)(g_Kh + ((size_t)(b * NH + n) * QLEN + i) * DH + d0) = p;
                    } else {
                        g_Vt[((size_t)(b * NH + n) * DH + d0) * QLEN + i] = __float2half(v0);
                        g_Vt[((size_t)(b * NH + n) * DH + d0 + 1) * QLEN + i] = __float2half(v1);
                    }
                } else {
                    const float2 wv = *(const float2*)(W + (size_t)r * DM + h);
                    *(float2*)(g_res + (size_t)r * DM + h) =
                        make_float2(v0 + wv.x, v1 + wv.y);
                }
            }
        }
    }
}

// ================= r_emb -> fp16 head-major ===================================
__global__ void __launch_bounds__(256) conv_r_kernel(const float* __restrict__ r_emb) {
    const int m = blockIdx.x;
    const int tid = threadIdx.x;
#pragma unroll
    for (int u = 0; u < 3; u++) {
        const int e = tid + u * 256;
        const int n = e >> 6, d = e & 63;
        g_Rh[((size_t)n * QLEN + m) * DH + d] =
            __float2half(r_emb[(size_t)m * NH * DH + e]);
    }
}

// ================= Kernel 2: fp16 flash rel-attention (R14 base + pair sync) ===
#define LH 72                                 // fp16 row stride (144 B)
#define LST 196                               // fp32 score row stride
#define SG_KR 0
#define SG_V  (192 * LH * 2)                  // 27648
#define SG_RB (SG_V + 64 * LH * 2)            // 36864
#define STAGE_BYTES (SG_RB + 128 * 4)         // 37376
#define OF_ST  (2 * STAGE_BYTES)              // 74752 : STs fp32 64x196
#define OF_PQ  (OF_ST + 64 * LST * 4)         // 124928 : P/Q fp16 64x72
#define OF_BW  (OF_PQ + 64 * LH * 2)          // 134144
#define OF_CSC (OF_BW + 256)
#define OF_LI  (OF_CSC + 256)
#define ATTN_SMEM_BYTES (OF_LI + 256)         // 134912

__global__ void __launch_bounds__(256, 1) attn_kernel(const float* __restrict__ r_bias,
                                                      const float* __restrict__ r_w_bias) {
    extern __shared__ char sm[];
    const uint32_t smb = smem_u32(sm);
    float* STs = (float*)(sm + OF_ST);
    __half* Ph = (__half*)(sm + OF_PQ);
    float* Bws = (float*)(sm + OF_BW);
    float* cscs = (float*)(sm + OF_CSC);
    float* lis  = (float*)(sm + OF_LI);

    const int bn = blockIdx.y;
    const int b = bn / NH, n = bn % NH;
    const int it = (gridDim.x - 1) - blockIdx.x;   // longest blocks first
    const int i0 = it * 64;
    const int tid = threadIdx.x;
    const int wid = tid >> 5, lane = tid & 31;
    const int wm = wid & 3;          // ST: 4 warp-rows x 16
    const int wn = wid >> 2;         // ST: 2 warp-cols x 96
    const int pr = wid >> 1;         // warp pair (0..3): owns PV/softmax rows pr*16..+16
    const int ws = wid & 1;          // sub-warp within pair
    const int lq = lane >> 2, lr = lane & 3;

    const __half* Kg0 = g_Kh + (size_t)(b * NH + n) * QLEN * DH;
    const __half* Vt0 = g_Vt + (size_t)(b * NH + n) * DH * QLEN;
    const __half* Rg0 = g_Rh + (size_t)n * QLEN * DH;

    // ---- prologue: Q tile into Ph, r_w_bias scaled ----
    {
        const __half* Qg = g_Qh + ((size_t)(b * NH + n) * QLEN + i0) * DH;
#pragma unroll
        for (int e2 = 0; e2 < 2; e2++) {
            const int e = tid + e2 * 256;
            const int row = e >> 3, c4 = e & 7;
            *(uint4*)((char*)Ph + row * (LH * 2) + c4 * 16) =
                *(const uint4*)(Qg + row * DH + c4 * 8);
        }
        if (tid < 64) Bws[tid] = r_w_bias[n * DH + tid] * SCALE_L2E;
    }

    // ---- prologue: cp.async stage 0 ----
    {
        const int m0 = 1984 - i0;
#pragma unroll
        for (int e2 = 0; e2 < 8; e2++) {
            const int e = tid + e2 * 256;
            const int row = e >> 3, c4 = e & 7;
            if (row < 64) {
                cp16(smb + SG_KR + row * (LH * 2) + c4 * 16, Kg0 + row * DH + c4 * 8, 16);
            } else if (row < 192) {
                const int rr = row - 64;
                const int m = m0 + rr;
                const uint32_t ok = (rr < 127 && m < QLEN) ? 16u : 0u;
                const __half* src = Rg0 + (size_t)(ok ? m : 0) * DH + c4 * 8;
                cp16(smb + SG_KR + row * (LH * 2) + c4 * 16, src, ok);
            } else {
                const int d = row - 192;
                cp16(smb + SG_V + d * (LH * 2) + c4 * 16, Vt0 + (size_t)d * QLEN + c4 * 8, 16);
            }
        }
        CP_COMMIT();
        if (tid < 128) {
            const int m = m0 + tid;
            ((float*)(sm + SG_RB))[tid] =
                (tid < 127 && m < QLEN) ? r_bias[m * NH + n] * SCALE_L2E : 0.f;
        }
    }
    __syncthreads();

    // Q fragments (rows wm*16+lq, +8): af = q, af2 = q + rwb (fp16 add)
    uint32_t af[4][4], af2[4][4];
    {
        const int qr = wm * 16 + lq;
        const char* Pb = (char*)Ph;
#pragma unroll
        for (int kk = 0; kk < 4; kk++) {
            const int c0 = kk * 16 + 2 * lr;
            af[kk][0] = *(const uint32_t*)(Pb + (qr * LH + c0) * 2);
            af[kk][1] = *(const uint32_t*)(Pb + ((qr + 8) * LH + c0) * 2);
            af[kk][2] = *(const uint32_t*)(Pb + (qr * LH + c0 + 8) * 2);
            af[kk][3] = *(const uint32_t*)(Pb + ((qr + 8) * LH + c0 + 8) * 2);
            const __half2 bw01 = __floats2half2_rn(Bws[c0], Bws[c0 + 1]);
            const __half2 bw89 = __floats2half2_rn(Bws[c0 + 8], Bws[c0 + 9]);
            __half2 t;
            t = __hadd2(*(const __half2*)&af[kk][0], bw01); af2[kk][0] = *(const uint32_t*)&t;
            t = __hadd2(*(const __half2*)&af[kk][1], bw01); af2[kk][1] = *(const uint32_t*)&t;
            t = __hadd2(*(const __half2*)&af[kk][2], bw89); af2[kk][2] = *(const uint32_t*)&t;
            t = __hadd2(*(const __half2*)&af[kk][3], bw89); af2[kk][3] = *(const uint32_t*)&t;
        }
    }

    float oacc[4][4];
#pragma unroll
    for (int nt = 0; nt < 4; nt++)
#pragma unroll
        for (int u = 0; u < 4; u++) oacc[nt][u] = 0.f;

    // softmax rows: pair pr owns rows pr*16..+16; 4 threads/row, 16 cols each
    const int srow = pr * 16 + ws * 8 + (lane >> 2);
    const int q4 = lane & 3;
    float mi = NEGINF, li = 0.f;

    const int njt = it + 1;
    for (int jt = 0; jt < njt; jt++) {
        const bool diag = (jt == it);
        const char* SGc = sm + (jt & 1) * STAGE_BYTES;
        const char* KRb = SGc + SG_KR;
        const char* Vtb = SGc + SG_V;
        const float* Rbcur = (const float*)(SGc + SG_RB);

        CP_WAIT0();
        __syncthreads();

        // ---- prefetch stage jt+1 ----
        if (jt + 1 < njt) {
            const int j0n = (jt + 1) * 64;
            const int m0n = 1984 - i0 + j0n;
            const uint32_t nb = smb + ((jt + 1) & 1) * STAGE_BYTES;
            const __half* Kgn = Kg0 + (size_t)j0n * DH;
#pragma unroll
            for (int e2 = 0; e2 < 8; e2++) {
                const int e = tid + e2 * 256;
                const int row = e >> 3, c4 = e & 7;
                if (row < 64) {
                    cp16(nb + SG_KR + row * (LH * 2) + c4 * 16, Kgn + row * DH + c4 * 8, 16);
                } else if (row < 192) {
                    const int rr = row - 64;
                    const int m = m0n + rr;
                    const uint32_t ok = (rr < 127 && m < QLEN) ? 16u : 0u;
                    const __half* src = Rg0 + (size_t)(ok ? m : 0) * DH + c4 * 8;
                    cp16(nb + SG_KR + row * (LH * 2) + c4 * 16, src, ok);
                } else {
                    const int d = row - 192;
                    cp16(nb + SG_V + d * (LH * 2) + c4 * 16,
                         Vt0 + (size_t)d * QLEN + j0n + c4 * 8, 16);
                }
            }
            CP_COMMIT();
            if (tid < 128) {
                const int m = m0n + tid;
                ((float*)(sm + ((jt + 1) & 1) * STAGE_BYTES + SG_RB))[tid] =
                    (tid < 127 && m < QLEN) ? r_bias[m * NH + n] * SCALE_L2E : 0.f;
            }
        }

        // ---- ST: K-cols use af2 (=(q+rwb)), R-cols use af (=q) ----
        {
            float sacc[12][4];
#pragma unroll
            for (int nt = 0; nt < 12; nt++)
#pragma unroll
                for (int u = 0; u < 4; u++) sacc[nt][u] = 0.f;
#pragma unroll
            for (int kk = 0; kk < 4; kk++) {
                const int c0 = kk * 16 + 2 * lr;
                uint32_t bf[12][2];
#pragma unroll
                for (int nt = 0; nt < 12; nt++) {
                    const int bc = wn * 96 + nt * 8 + lq;
                    bf[nt][0] = *(const uint32_t*)(KRb + (bc * LH + c0) * 2);
                    bf[nt][1] = *(const uint32_t*)(KRb + (bc * LH + c0 + 8) * 2);
                }
#pragma unroll
                for (int nt = 0; nt < 12; nt++) {
                    const bool kcol = (wn == 0) && (nt < 8);   // block cols < 64
                    MMA_FP16(sacc[nt], kcol ? af2[kk] : af[kk], bf[nt]);
                }
            }
            const int row0 = wm * 16 + lq;
#pragma unroll
            for (int nt = 0; nt < 12; nt++) {
                const int col = wn * 96 + nt * 8 + lr * 2;
                *(float2*)&STs[row0 * LST + col] = make_float2(sacc[nt][0], sacc[nt][1]);
                *(float2*)&STs[(row0 + 8) * LST + col] = make_float2(sacc[nt][2], sacc[nt][3]);
            }
        }
        __syncthreads();

        // ---- softmax (pair-local rows; no Bk term) ----
        {
            const int toff = 127 - srow;
            const int roff = 63 - srow;
            float z[16];
            float lmax = NEGINF;
#pragma unroll
            for (int c = 0; c < 16; c++) {
                const int jl = q4 + 4 * c;
                float s = STs[srow * LST + jl] + STs[srow * LST + toff + jl] +
                          Rbcur[roff + jl];
                if (diag && jl > srow) s = NEGINF;
                z[c] = s;
                lmax = fmaxf(lmax, s);
            }
            lmax = fmaxf(lmax, __shfl_xor_sync(0xffffffffu, lmax, 1));
            lmax = fmaxf(lmax, __shfl_xor_sync(0xffffffffu, lmax, 2));
            const float mnew = fmaxf(mi, lmax);
            const float csc = exp2_poly(mi - mnew);
            float lsum = 0.f;
#pragma unroll
            for (int c = 0; c < 16; c++) {
                const float p = exp2_poly(z[c] - mnew);
                Ph[srow * LH + q4 + 4 * c] = __float2half(p);
                lsum += p;
            }
            lsum += __shfl_xor_sync(0xffffffffu, lsum, 1);
            lsum += __shfl_xor_sync(0xffffffffu, lsum, 2);
            li = li * csc + lsum;
            mi = mnew;
            if (q4 == 0) cscs[srow] = csc;
        }
        BAR_PAIR(1 + pr);   // pair-scope: softmax rows -> PV of same pair only

        // ---- O = O*csc + P.V   (pair rows pr*16..+16; sub-warp cols ws*32..) ----
        {
            const int ar = pr * 16 + lq;
            const float c0 = cscs[ar];
            const float c1 = cscs[ar + 8];
#pragma unroll
            for (int nt = 0; nt < 4; nt++) {
                oacc[nt][0] *= c0; oacc[nt][1] *= c0;
                oacc[nt][2] *= c1; oacc[nt][3] *= c1;
            }
            const char* Pb = (char*)Ph;
#pragma unroll
            for (int kk = 0; kk < 4; kk++) {
                const int c0k = kk * 16 + 2 * lr;
                uint32_t pa[4];
                pa[0] = *(const uint32_t*)(Pb + (ar * LH + c0k) * 2);
                pa[1] = *(const uint32_t*)(Pb + ((ar + 8) * LH + c0k) * 2);
                pa[2] = *(const uint32_t*)(Pb + (ar * LH + c0k + 8) * 2);
                pa[3] = *(const uint32_t*)(Pb + ((ar + 8) * LH + c0k + 8) * 2);
#pragma unroll
                for (int nt = 0; nt < 4; nt++) {
                    const int d = ws * 32 + nt * 8 + lq;
                    uint32_t vb[2];
                    vb[0] = *(const uint32_t*)(Vtb + (d * LH + c0k) * 2);
                    vb[1] = *(const uint32_t*)(Vtb + (d * LH + c0k + 8) * 2);
                    MMA_FP16(oacc[nt], pa, vb);
                }
            }
        }
    }

    // ---- epilogue: write attn_vec in fp16 for the O-projection ----
    if (q4 == 0) lis[srow] = li;
    __syncthreads();
    {
        const int r0 = pr * 16 + lq;
        const float inv0 = 1.f / lis[r0];
        const float inv1 = 1.f / lis[r0 + 8];
#pragma unroll
        for (int nt = 0; nt < 4; nt++) {
            const int d = ws * 32 + nt * 8 + lr * 2;
            __half* p0 = g_atth + ((size_t)(i0 + r0) * BSZ + b) * DM + n * DH + d;
            *(__half2*)p0 = __floats2half2_rn(oacc[nt][0] * inv0, oacc[nt][1] * inv0);
            __half* p1 = g_atth + ((size_t)(i0 + r0 + 8) * BSZ + b) * DM + n * DH + d;
            *(__half2*)p1 = __floats2half2_rn(oacc[nt][2] * inv1, oacc[nt][3] * inv1);
        }
    }
}

// ================= Kernel 4: LayerNorm ========================================
__device__ __forceinline__ float block_sum(float v, float* red) {
#pragma unroll
    for (int o = 16; o > 0; o >>= 1) v += __shfl_xor_sync(0xffffffffu, v, o);
    const int w = threadIdx.x >> 5;
    if ((threadIdx.x & 31) == 0) red[w] = v;
    __syncthreads();
    if (threadIdx.x < 32) {
        float t = (threadIdx.x < 8) ? red[threadIdx.x] : 0.f;
#pragma unroll
        for (int o = 4; o > 0; o >>= 1) t += __shfl_xor_sync(0xffffffffu, t, o);
        if (threadIdx.x == 0) red[0] = t;
    }
    __syncthreads();
    const float r = red[0];
    __syncthreads();
    return r;
}

__global__ void __launch_bounds__(256) ln_kernel(const float* __restrict__ gamma,
                                                 const float* __restrict__ beta,
                                                 float* __restrict__ out) {
    __shared__ float red[8];
    const int r = blockIdx.x;
    const float* x = g_res + (size_t)r * DM;
    const int tid = threadIdx.x;
    float v[3];
#pragma unroll
    for (int u = 0; u < 3; u++) v[u] = x[tid + u * 256];
    const float total = block_sum(v[0] + v[1] + v[2], red);
    const float mu = total * (1.f / DM);
    float sq = 0.f;
#pragma unroll
    for (int u = 0; u < 3; u++) { const float d = v[u] - mu; sq += d * d; }
    const float var = block_sum(sq, red) * (1.f / DM);
    const float inv = rsqrtf(var + 1e-5f);
#pragma unroll
    for (int u = 0; u < 3; u++) {
        const int c = tid + u * 256;
        out[(size_t)r * DM + c] = (v[u] - mu) * inv * gamma[c] + beta[c];
    }
}

// ================= launch =====================================================
extern "C" void kernel_launch(void* const* d_in, const int* in_sizes, int n_in,
                              void* d_out, int out_size) {
    const float* w        = (const float*)d_in[0];
    const float* r_emb    = (const float*)d_in[1];
    const float* r_w_bias = (const float*)d_in[2];
    const float* r_bias   = (const float*)d_in[3];
    const float* qkv_w    = (const float*)d_in[4];
    const float* o_w      = (const float*)d_in[5];
    const float* ln_g     = (const float*)d_in[6];
    const float* ln_b     = (const float*)d_in[7];
    float* out = (float*)d_out;

    __half *g_wh_p = nullptr, *g_qkvwh_p = nullptr, *g_owh_p = nullptr, *g_atth_p = nullptr;
    cudaGetSymbolAddress((void**)&g_wh_p, g_wh);
    cudaGetSymbolAddress((void**)&g_qkvwh_p, g_qkvwh);
    cudaGetSymbolAddress((void**)&g_owh_p, g_owh);
    cudaGetSymbolAddress((void**)&g_atth_p, g_atth);

    f2h_kernel<<<1024, 256>>>(w, qkv_w, o_w);
    conv_r_kernel<<<QLEN, 256>>>(r_emb);

    (void)cudaFuncSetAttribute(mma_gemm_kernel<0>,
                               cudaFuncAttributeMaxDynamicSharedMemorySize, PROJ_SMEM_BYTES);
    (void)cudaFuncSetAttribute(mma_gemm_kernel<1>,
                               cudaFuncAttributeMaxDynamicSharedMemorySize, PROJ_SMEM_BYTES);

    // QKV projection -> fp16 Q/K/Vt
    mma_gemm_kernel<0><<<dim3(QLEN * BSZ / PBM, 3 * DM / PBN), 256, PROJ_SMEM_BYTES>>>(
        g_wh_p, g_qkvwh_p, nullptr, DM);

    // fp16 flash rel-attention (R14 base + pair-local softmax->PV)
    (void)cudaFuncSetAttribute(attn_kernel, cudaFuncAttributeMaxDynamicSharedMemorySize,
                               ATTN_SMEM_BYTES);
    attn_kernel<<<dim3(QLEN / 64, BSZ * NH), 256, ATTN_SMEM_BYTES>>>(r_bias, r_w_bias);

    // O-projection + residual
    mma_gemm_kernel<1><<<dim3(QLEN * BSZ / PBM, DM / PBN), 256, PROJ_SMEM_BYTES>>>(
        g_atth_p, g_owh_p, w, DM);

    ln_kernel<<<QLEN * BSZ, 256>>>(ln_g, ln_b, out);
}